// round 4
// baseline (speedup 1.0000x reference)
#include <cuda_runtime.h>
#include <cstdint>

// Problem constants
#define NGEN  10
#define BATCH 4096
#define NZ    128
#define HID1  512
#define HID2  1024
#define IMG   784

// GEMM tiling
#define TM 128
#define TN 128
#define TK 16
#define MAX_TILES (BATCH / TM + NGEN)   // 42: sum of ceil(n_g/TM) <= B/TM + G

// ---------------- device scratch (no allocations allowed) ----------------
__device__ int   d_cnt[NGEN];
__device__ int   d_cursor[NGEN];
__device__ int   d_off[NGEN + 1];
__device__ int   d_tileOff[NGEN + 1];
__device__ int   d_perm[BATCH];
__device__ float d_h1[BATCH * HID1];   // 8 MB,  permuted row order
__device__ float d_h2[BATCH * HID2];   // 16 MB, permuted row order

// ---------------- grouping kernels ----------------
__global__ void k_init() {
    int t = threadIdx.x;
    if (t < NGEN) { d_cnt[t] = 0; d_cursor[t] = 0; }
}

__global__ void k_count(const int* __restrict__ gi) {
    int i = blockIdx.x * blockDim.x + threadIdx.x;
    if (i < BATCH) atomicAdd(&d_cnt[gi[i]], 1);
}

__global__ void k_scan() {
    if (threadIdx.x == 0) {
        int s = 0, t = 0;
        for (int g = 0; g < NGEN; g++) {
            d_off[g] = s; d_tileOff[g] = t;
            s += d_cnt[g];
            t += (d_cnt[g] + TM - 1) / TM;
        }
        d_off[NGEN] = s; d_tileOff[NGEN] = t;
    }
}

__global__ void k_scatter(const int* __restrict__ gi) {
    int i = blockIdx.x * blockDim.x + threadIdx.x;
    if (i < BATCH) {
        int g = gi[i];
        int p = d_off[g] + atomicAdd(&d_cursor[g], 1);
        d_perm[p] = i;   // output per sample is row-independent => deterministic
    }
}

// ---------------- packed fp32x2 helpers ----------------
__device__ __forceinline__ unsigned long long fma2(unsigned long long a,
                                                   unsigned long long b,
                                                   unsigned long long c) {
    unsigned long long d;
    asm("fma.rn.f32x2 %0, %1, %2, %3;" : "=l"(d) : "l"(a), "l"(b), "l"(c));
    return d;
}

__device__ __forceinline__ unsigned long long dup2(float f) {
    unsigned int u = __float_as_uint(f);
    return ((unsigned long long)u << 32) | (unsigned long long)u;
}

// ---------------- grouped SGEMM ----------------
// LAYER 1: A = gather(z via perm), C = d_h1, relu
// LAYER 2: A = d_h1,               C = d_h2, relu
// LAYER 3: A = d_h2,               C = scatter(out via perm), tanh
template <int K, int N, int LAYER>
__global__ __launch_bounds__(256, 2)
void gemm_kernel(const float* __restrict__ Ain,
                 const float* __restrict__ W,
                 const float* __restrict__ bias,
                 float* __restrict__ Cout) {
    constexpr int ASTR = 2 * TM + 2;             // 258 floats/row (dup A + pad)
    __shared__ __align__(16) float As[TK][ASTR]; // A duplicated: (a,a) pairs
    __shared__ __align__(16) float Bs[TK][TN];   // B plain K-major

    const int bx = blockIdx.x;
    if (bx >= d_tileOff[NGEN]) return;

    int g = 0;
#pragma unroll
    for (int i = 1; i < NGEN; i++)
        if (d_tileOff[i] <= bx) g = i;

    const int m_base = d_off[g] + (bx - d_tileOff[g]) * TM;
    const int m_end  = d_off[g + 1];
    const int n0     = blockIdx.y * TN;

    const float* A = (LAYER == 1) ? Ain : (LAYER == 2 ? d_h1 : d_h2);
    float*       C = (LAYER == 3) ? Cout : (LAYER == 1 ? d_h1 : d_h2);
    const float* Wg = W + (size_t)g * K * N;
    const float* bg = bias + g * N;

    const int tid = threadIdx.x;
    const int tx  = tid & 15;        // 0..15
    const int ty  = tid >> 4;        // 0..15

    // A tile load mapping: 2 float4 per thread; 4 lanes per row (coalesced 64B)
    const int ra0 = tid >> 2;        // row 0..63 (q=0); +64 for q=1
    const int c4  = tid & 3;         // which 4-wide k sub-chunk
    const float* aRow0 = nullptr;
    const float* aRow1 = nullptr;
    {
        int m0 = m_base + ra0;
        int m1 = m_base + ra0 + 64;
        if (m0 < m_end) {
            long s = (LAYER == 1) ? (long)d_perm[m0] : (long)m0;
            aRow0 = A + s * (long)K + c4 * 4;
        }
        if (m1 < m_end) {
            long s = (LAYER == 1) ? (long)d_perm[m1] : (long)m1;
            aRow1 = A + s * (long)K + c4 * 4;
        }
    }

    // B tile load mapping: row ty (k), cols nb..nb+7
    const int nb = n0 + tx * 8;

    // Accumulators: 8 rows x 4 column-pairs, each holds (col 2p, col 2p+1)
    unsigned long long acc[8][4];
#pragma unroll
    for (int i = 0; i < 8; i++)
#pragma unroll
        for (int j = 0; j < 4; j++) acc[i][j] = 0ull;

#pragma unroll 1
    for (int k0 = 0; k0 < K; k0 += TK) {
        float4 a0 = make_float4(0.f, 0.f, 0.f, 0.f);
        float4 a1 = a0, b0 = a0, b1 = a0;
        if (aRow0) a0 = *reinterpret_cast<const float4*>(aRow0 + k0);
        if (aRow1) a1 = *reinterpret_cast<const float4*>(aRow1 + k0);
        const float* wRow = Wg + (size_t)(k0 + ty) * N + nb;
        if ((N % TN == 0) || (nb     < N)) b0 = *reinterpret_cast<const float4*>(wRow);
        if ((N % TN == 0) || (nb + 4 < N)) b1 = *reinterpret_cast<const float4*>(wRow + 4);

        __syncthreads();
        {
            const float* av = reinterpret_cast<const float*>(&a0);
#pragma unroll
            for (int u = 0; u < 4; u++)
                *reinterpret_cast<unsigned long long*>(&As[c4 * 4 + u][2 * ra0]) = dup2(av[u]);
            av = reinterpret_cast<const float*>(&a1);
#pragma unroll
            for (int u = 0; u < 4; u++)
                *reinterpret_cast<unsigned long long*>(&As[c4 * 4 + u][2 * (ra0 + 64)]) = dup2(av[u]);

            *reinterpret_cast<float4*>(&Bs[ty][tx * 8])     = b0;
            *reinterpret_cast<float4*>(&Bs[ty][tx * 8 + 4]) = b1;
        }
        __syncthreads();

#pragma unroll
        for (int kk = 0; kk < TK; kk++) {
            unsigned long long ar[8], br[4];
#pragma unroll
            for (int i = 0; i < 8; i++)
                ar[i] = *reinterpret_cast<const unsigned long long*>(&As[kk][2 * (ty * 8 + i)]);
#pragma unroll
            for (int j = 0; j < 4; j++)
                br[j] = *reinterpret_cast<const unsigned long long*>(&Bs[kk][2 * (tx + 16 * j)]);
#pragma unroll
            for (int i = 0; i < 8; i++)
#pragma unroll
                for (int j = 0; j < 4; j++)
                    acc[i][j] = fma2(ar[i], br[j], acc[i][j]);
        }
    }

    // Epilogue: bias + activation + store (float2 per acc pair)
#pragma unroll
    for (int j = 0; j < 4; j++) {
        const int n = n0 + 2 * (tx + 16 * j);
        const bool nok = (N % TN == 0) || (n < N);   // N even => n and n+1 together
        float bv0 = 0.f, bv1 = 0.f;
        if (nok) { bv0 = bg[n]; bv1 = bg[n + 1]; }
#pragma unroll
        for (int i = 0; i < 8; i++) {
            const int m = m_base + ty * 8 + i;
            if (m >= m_end || !nok) continue;
            float v0 = __uint_as_float((unsigned int)(acc[i][j])) + bv0;
            float v1 = __uint_as_float((unsigned int)(acc[i][j] >> 32)) + bv1;
            if (LAYER == 3) { v0 = tanhf(v0); v1 = tanhf(v1); }
            else            { v0 = fmaxf(v0, 0.f); v1 = fmaxf(v1, 0.f); }
            const long r = (LAYER == 3) ? (long)d_perm[m] : (long)m;
            *reinterpret_cast<float2*>(&C[r * (long)N + n]) = make_float2(v0, v1);
        }
    }
}

// ---------------- launch ----------------
extern "C" void kernel_launch(void* const* d_in, const int* in_sizes, int n_in,
                              void* d_out, int out_size) {
    const float* z  = (const float*)d_in[0];
    const int*   gi = (const int*)  d_in[1];
    const float* W1 = (const float*)d_in[2];
    const float* b1 = (const float*)d_in[3];
    const float* W2 = (const float*)d_in[4];
    const float* b2 = (const float*)d_in[5];
    const float* W3 = (const float*)d_in[6];
    const float* b3 = (const float*)d_in[7];
    float* out = (float*)d_out;

    k_init<<<1, 32>>>();
    k_count<<<BATCH / 256, 256>>>(gi);
    k_scan<<<1, 1>>>();
    k_scatter<<<BATCH / 256, 256>>>(gi);

    dim3 blk(256);
    gemm_kernel<NZ,   HID1, 1><<<dim3(MAX_TILES, HID1 / TN), blk>>>(z,       W1, b1, nullptr);
    gemm_kernel<HID1, HID2, 2><<<dim3(MAX_TILES, HID2 / TN), blk>>>(nullptr, W2, b2, nullptr);
    gemm_kernel<HID2, IMG,  3><<<dim3(MAX_TILES, (IMG + TN - 1) / TN), blk>>>(nullptr, W3, b3, out);
}

// round 6
// speedup vs baseline: 1.0426x; 1.0426x over previous
#include <cuda_runtime.h>
#include <cstdint>

// Problem constants
#define NGEN  10
#define BATCH 4096
#define NZ    128
#define HID1  512
#define HID2  1024
#define IMG   784

// GEMM tiling: TM=64 x TN=128, 128 threads, 8x8 outputs/thread, occ 4
#define TM 64
#define TN 128
#define TK 16
#define MAX_TILES (BATCH / TM + NGEN)   // 74

// ---------------- device scratch (no allocations allowed) ----------------
__device__ int   d_off[NGEN + 1];
__device__ int   d_tileOff[NGEN + 1];
__device__ int   d_perm[BATCH];
__device__ float d_h1[BATCH * HID1];   // 8 MB,  permuted row order
__device__ float d_h2[BATCH * HID2];   // 16 MB, permuted row order

// ---------------- fused grouping: count + scan + scatter, one block ------
#define GT 512
__global__ void k_group(const int* __restrict__ gi) {
    __shared__ int s_cnt[NGEN];
    __shared__ int s_cur[NGEN];
    const int t = threadIdx.x;
    if (t < NGEN) s_cnt[t] = 0;
    __syncthreads();
    int gloc[BATCH / GT];
#pragma unroll
    for (int r = 0; r < BATCH / GT; r++) {
        gloc[r] = gi[t + GT * r];
        atomicAdd(&s_cnt[gloc[r]], 1);
    }
    __syncthreads();
    if (t == 0) {
        int s = 0, tile = 0;
        for (int g = 0; g < NGEN; g++) {
            d_off[g] = s; d_tileOff[g] = tile; s_cur[g] = s;
            s += s_cnt[g];
            tile += (s_cnt[g] + TM - 1) / TM;
        }
        d_off[NGEN] = s; d_tileOff[NGEN] = tile;
    }
    __syncthreads();
    // order within a group is irrelevant: each sample's row computation is
    // independent and scattered back to its original row => bitwise-stable.
#pragma unroll
    for (int r = 0; r < BATCH / GT; r++) {
        int p = atomicAdd(&s_cur[gloc[r]], 1);
        d_perm[p] = t + GT * r;
    }
}

// ---------------- packed fp32x2 helpers ----------------
__device__ __forceinline__ unsigned long long fma2(unsigned long long a,
                                                   unsigned long long b,
                                                   unsigned long long c) {
    unsigned long long d;
    asm("fma.rn.f32x2 %0, %1, %2, %3;" : "=l"(d) : "l"(a), "l"(b), "l"(c));
    return d;
}

__device__ __forceinline__ unsigned long long dup2(float f) {
    unsigned int u = __float_as_uint(f);
    return ((unsigned long long)u << 32) | (unsigned long long)u;
}

__device__ __forceinline__ float fast_tanh(float x) {
    float y;
    asm("tanh.approx.f32 %0, %1;" : "=f"(y) : "f"(x));
    return y;
}

// ---------------- grouped SGEMM (register-prefetch pipelined) ----------------
// LAYER 1: A = gather(z via perm), C = d_h1, relu
// LAYER 2: A = d_h1,               C = d_h2, relu
// LAYER 3: A = d_h2,               C = scatter(out via perm), tanh
template <int K, int N, int LAYER>
__global__ __launch_bounds__(128, 4)
void gemm_kernel(const float* __restrict__ Ain,
                 const float* __restrict__ W,
                 const float* __restrict__ bias,
                 float* __restrict__ Cout) {
    constexpr int ASTR = 2 * TM + 2;             // 130 floats/row (dup A + pad)
    __shared__ __align__(16) float As[TK][ASTR]; // A duplicated: (a,a) pairs
    __shared__ __align__(16) float Bs[TK][TN];   // B plain K-major

    const int bx = blockIdx.x;
    if (bx >= d_tileOff[NGEN]) return;

    int g = 0;
#pragma unroll
    for (int i = 1; i < NGEN; i++)
        if (d_tileOff[i] <= bx) g = i;

    const int m_base = d_off[g] + (bx - d_tileOff[g]) * TM;
    const int m_end  = d_off[g + 1];
    const int n0     = blockIdx.y * TN;

    const float* A = (LAYER == 1) ? Ain : (LAYER == 2 ? d_h1 : d_h2);
    float*       C = (LAYER == 3) ? Cout : (LAYER == 1 ? d_h1 : d_h2);
    const float* Wg = W + (size_t)g * K * N;
    const float* bg = bias + g * N;

    const int tid = threadIdx.x;
    const int tx  = tid & 15;        // 0..15 (column groups)
    const int ty  = tid >> 4;        // 0..7  (row groups of 8)

    // A tile load mapping: 2 float4/thread; rows ra0 and ra0+32
    const int ra0 = tid >> 2;        // 0..31
    const int c4  = tid & 3;         // k sub-chunk
    const float* aRow0 = nullptr;
    const float* aRow1 = nullptr;
    {
        int m0 = m_base + ra0;
        int m1 = m_base + ra0 + 32;
        if (m0 < m_end) {
            long s = (LAYER == 1) ? (long)d_perm[m0] : (long)m0;
            aRow0 = A + s * (long)K + c4 * 4;
        }
        if (m1 < m_end) {
            long s = (LAYER == 1) ? (long)d_perm[m1] : (long)m1;
            aRow1 = A + s * (long)K + c4 * 4;
        }
    }

    // B tile load mapping: 4 float4/thread; rows brow, brow+8; cols nb, nb+4
    const int brow = tid >> 4;       // 0..7
    const int nb   = n0 + tx * 8;
    const bool nok0 = (N % TN == 0) || (nb     < N);
    const bool nok1 = (N % TN == 0) || (nb + 4 < N);

    // Accumulators: 8 rows x 4 column-pairs
    unsigned long long acc[8][4];
#pragma unroll
    for (int i = 0; i < 8; i++)
#pragma unroll
        for (int j = 0; j < 4; j++) acc[i][j] = 0ull;

    // Prefetch registers
    float4 a0, a1, b00, b01, b10, b11;

    auto ldg = [&](int k0) {
        const float4 z4 = make_float4(0.f, 0.f, 0.f, 0.f);
        a0 = z4; a1 = z4; b00 = z4; b01 = z4; b10 = z4; b11 = z4;
        if (aRow0) a0 = *reinterpret_cast<const float4*>(aRow0 + k0);
        if (aRow1) a1 = *reinterpret_cast<const float4*>(aRow1 + k0);
        const float* w0 = Wg + (size_t)(k0 + brow) * N + nb;
        const float* w1 = Wg + (size_t)(k0 + brow + 8) * N + nb;
        if (nok0) { b00 = *reinterpret_cast<const float4*>(w0);
                    b10 = *reinterpret_cast<const float4*>(w1); }
        if (nok1) { b01 = *reinterpret_cast<const float4*>(w0 + 4);
                    b11 = *reinterpret_cast<const float4*>(w1 + 4); }
    };

    auto sts = [&]() {
        const float* av = reinterpret_cast<const float*>(&a0);
#pragma unroll
        for (int u = 0; u < 4; u++)
            *reinterpret_cast<unsigned long long*>(&As[c4 * 4 + u][2 * ra0]) = dup2(av[u]);
        av = reinterpret_cast<const float*>(&a1);
#pragma unroll
        for (int u = 0; u < 4; u++)
            *reinterpret_cast<unsigned long long*>(&As[c4 * 4 + u][2 * (ra0 + 32)]) = dup2(av[u]);
        *reinterpret_cast<float4*>(&Bs[brow][tx * 8])         = b00;
        *reinterpret_cast<float4*>(&Bs[brow][tx * 8 + 4])     = b01;
        *reinterpret_cast<float4*>(&Bs[brow + 8][tx * 8])     = b10;
        *reinterpret_cast<float4*>(&Bs[brow + 8][tx * 8 + 4]) = b11;
    };

    ldg(0);
#pragma unroll 1
    for (int k0 = 0; k0 < K; k0 += TK) {
        __syncthreads();        // previous chunk's compute done reading smem
        sts();
        __syncthreads();
        if (k0 + TK < K) ldg(k0 + TK);   // overlap with compute below

#pragma unroll
        for (int kk = 0; kk < TK; kk++) {
            unsigned long long ar[8], br[4];
#pragma unroll
            for (int i = 0; i < 8; i++)   // broadcast (same addr across tx)
                ar[i] = *reinterpret_cast<const unsigned long long*>(&As[kk][2 * (ty * 8 + i)]);
#pragma unroll
            for (int j = 0; j < 4; j++)   // 16 distinct 8B, 2-way broadcast
                br[j] = *reinterpret_cast<const unsigned long long*>(&Bs[kk][2 * (tx + 16 * j)]);
#pragma unroll
            for (int i = 0; i < 8; i++)
#pragma unroll
                for (int j = 0; j < 4; j++)
                    acc[i][j] = fma2(ar[i], br[j], acc[i][j]);
        }
    }

    // Epilogue: bias + activation + store (float2 per acc pair)
#pragma unroll
    for (int j = 0; j < 4; j++) {
        const int n = n0 + 2 * (tx + 16 * j);
        const bool nok = (N % TN == 0) || (n < N);   // N even: n, n+1 together
        float bv0 = 0.f, bv1 = 0.f;
        if (nok) { bv0 = bg[n]; bv1 = bg[n + 1]; }
#pragma unroll
        for (int i = 0; i < 8; i++) {
            const int m = m_base + ty * 8 + i;
            if (m >= m_end || !nok) continue;
            float v0 = __uint_as_float((unsigned int)(acc[i][j])) + bv0;
            float v1 = __uint_as_float((unsigned int)(acc[i][j] >> 32)) + bv1;
            if (LAYER == 3) { v0 = fast_tanh(v0); v1 = fast_tanh(v1); }
            else            { v0 = fmaxf(v0, 0.f); v1 = fmaxf(v1, 0.f); }
            const long r = (LAYER == 3) ? (long)d_perm[m] : (long)m;
            *reinterpret_cast<float2*>(&C[r * (long)N + n]) = make_float2(v0, v1);
        }
    }
}

// ---------------- launch ----------------
extern "C" void kernel_launch(void* const* d_in, const int* in_sizes, int n_in,
                              void* d_out, int out_size) {
    const float* z  = (const float*)d_in[0];
    const int*   gi = (const int*)  d_in[1];
    const float* W1 = (const float*)d_in[2];
    const float* b1 = (const float*)d_in[3];
    const float* W2 = (const float*)d_in[4];
    const float* b2 = (const float*)d_in[5];
    const float* W3 = (const float*)d_in[6];
    const float* b3 = (const float*)d_in[7];
    float* out = (float*)d_out;

    k_group<<<1, GT>>>(gi);

    dim3 blk(128);
    gemm_kernel<NZ,   HID1, 1><<<dim3(MAX_TILES, HID1 / TN), blk>>>(z,       W1, b1, nullptr);
    gemm_kernel<HID1, HID2, 2><<<dim3(MAX_TILES, HID2 / TN), blk>>>(nullptr, W2, b2, nullptr);
    gemm_kernel<HID2, IMG,  3><<<dim3(MAX_TILES, (IMG + TN - 1) / TN), blk>>>(nullptr, W3, b3, out);
}